// round 13
// baseline (speedup 1.0000x reference)
#include <cuda_runtime.h>
#include <math_constants.h>

// Problem constants
#define LQ   15876          // L = 126*126 patches
#define HO   126
#define D    27
#define DP   28             // padded dim; K pad = 1.0 (ssum trick), Q pad = 0
#define SPLIT 9             // split-K over keys (15876 = 9 * 1764)
#define BQ   256            // threads per CTA (1 query per thread)
#define BK   252            // key tile in smem (1764 = 7 * 252, no tail)
#define BATCH 28            // keys per mask batch (252 = 9 * 28)
#define NQB  64             // 8x8 CTA tiles of 16x16 queries (covers 126x126)
#define CH   (LQ / SPLIT)   // 1764 keys per chunk
#define DP2  (DP / 2)       // 14 packed f32x2 values
#define SKIP_THR 18.0f      // log2 skip; measured dropped mass ~1e-9 at 22

typedef unsigned long long u64;

// Scratch (no allocations allowed -> device globals)
__device__ __align__(16) float g_K[LQ * DP];          // x patches (keys/vals)
__device__ __align__(16) float g_Q[LQ * DP];          // y patches (queries)
__device__ float g_yyc[LQ];                            // ||X_m||^2 * log2e/0.35
__device__ float g_pm[SPLIT * LQ];                     // partial max (log2 dom)
__device__ __align__(16) float g_pacc[SPLIT * LQ * DP]; // [..27] holds ssum
__device__ __align__(16) float g_outP[LQ * DP];        // attention out patches

__device__ __forceinline__ float ex2(float x) {
    float r;
    asm("ex2.approx.ftz.f32 %0, %1;" : "=f"(r) : "f"(x));
    return r;
}
__device__ __forceinline__ u64 pack2(float a, float b) {
    u64 r;
    asm("mov.b64 %0, {%1, %2};" : "=l"(r) : "f"(a), "f"(b));
    return r;
}
__device__ __forceinline__ void unpack2(u64 v, float& a, float& b) {
    asm("mov.b64 {%0, %1}, %2;" : "=f"(a), "=f"(b) : "l"(v));
}
// d = a*b + c  (packed 2x fp32)
__device__ __forceinline__ u64 fma2v(u64 a, u64 b, u64 c) {
    u64 d;
    asm("fma.rn.f32x2 %0, %1, %2, %3;" : "=l"(d) : "l"(a), "l"(b), "l"(c));
    return d;
}
__device__ __forceinline__ u64 add2v(u64 a, u64 b) {
    u64 d;
    asm("add.rn.f32x2 %0, %1, %2;" : "=l"(d) : "l"(a), "l"(b));
    return d;
}
__device__ __forceinline__ u64 mul2v(u64 a, u64 b) {
    u64 d;
    asm("mul.rn.f32x2 %0, %1, %2;" : "=l"(d) : "l"(a), "l"(b));
    return d;
}
// load two adjacent u64 (16B) from shared
__device__ __forceinline__ void lds_v2u64(u64& a, u64& b, const void* p) {
    asm("ld.shared.v2.b64 {%0, %1}, [%2];"
        : "=l"(a), "=l"(b) : "l"((size_t)__cvta_generic_to_shared(p)));
}

// ---------------------------------------------------------------------------
// Kernel A: patch extraction + key squared norms. K pad=1.0, Q pad=0.0
// ---------------------------------------------------------------------------
__global__ void extract_kernel(const float* __restrict__ x,
                               const float* __restrict__ y) {
    int m = blockIdx.x * blockDim.x + threadIdx.x;
    if (m >= LQ) return;
    int ph = m / HO, pw = m % HO;
    const float YSC = 1.4426950408889634f / 0.35f;   // log2e / (h^2 + 0.1)
    float yy = 0.f;
#pragma unroll
    for (int c = 0; c < 3; c++)
#pragma unroll
        for (int ki = 0; ki < 3; ki++)
#pragma unroll
            for (int kj = 0; kj < 3; kj++) {
                int j = c * 9 + ki * 3 + kj;
                float vx = x[c * 16384 + (ph + ki) * 128 + (pw + kj)];
                float vy = y[c * 16384 + (ph + ki) * 128 + (pw + kj)];
                g_K[m * DP + j] = vx;
                g_Q[m * DP + j] = vy;
                yy = fmaf(vx, vx, yy);
            }
    g_K[m * DP + 27] = 1.0f;     // ssum-in-accumulator trick
    g_Q[m * DP + 27] = 0.0f;     // keeps dot product exact
    g_yyc[m] = yy * YSC;
}

// ---------------------------------------------------------------------------
// Kernel B: flash attention, split-K, packed f32x2, BATCHED threshold skip.
// Per 28-key batch: (1) fast pass computes 28 independent dots and a 28-bit
// relevance mask (no votes, no branches); (2) one redux.sync.or unions the
// mask across the warp; (3) bit-scan slow pass recomputes the dot and does
// the online-softmax update only for flagged keys. Threshold uses the
// pre-batch mmax (conservative -> >= mass of the per-key variant).
// acc[27] accumulates the softmax mass (K pad element = 1).
// ---------------------------------------------------------------------------
__global__ __launch_bounds__(BQ, 2) void attn_kernel() {
    __shared__ __align__(16) float sK[BK * DP];
    __shared__ float sY[BK];

    int tid = threadIdx.x;
    int w = tid >> 5;                       // warp 0..7
    int lane = tid & 31;
    // CTA tile: 16x16 queries at (bh*16, bw*16); warp subtile 4x8
    int bh = blockIdx.x >> 3, bw = blockIdx.x & 7;
    int qrow = min(bh * 16 + (w >> 1) * 4 + (lane >> 3), HO - 1);
    int qcol = min(bw * 16 + (w & 1) * 8 + (lane & 7), HO - 1);
    int ql = qrow * HO + qcol;

    int k0 = blockIdx.y * CH;

    const float S2 = 2.0f * 1.4426950408889634f / 0.35f;

    u64 qv[DP2];
#pragma unroll
    for (int p = 0; p < DP2 / 2; p++) {
        ulonglong2 t = ((const ulonglong2*)&g_Q[ql * DP])[p];
        qv[2 * p] = t.x; qv[2 * p + 1] = t.y;
    }
    u64 acc[DP2];
#pragma unroll
    for (int j = 0; j < DP2; j++) acc[j] = 0ull;
    float mmax = -CUDART_INF_F;

#pragma unroll 1
    for (int tile = 0; tile < CH / BK; tile++) {
        int kt = k0 + tile * BK;
        for (int t = tid; t < BK * (DP / 4); t += BQ) {
            ((float4*)sK)[t] = ((const float4*)g_K)[kt * (DP / 4) + t];
        }
        for (int t = tid; t < BK; t += BQ) sY[t] = g_yyc[kt + t];
        __syncthreads();

#pragma unroll 1
        for (int b = 0; b < BK; b += BATCH) {
            float thr = mmax - SKIP_THR;
            unsigned mask = 0u;
            // ---- fast pass: 28 independent dots, build relevance mask ----
#pragma unroll 4
            for (int i = 0; i < BATCH; i++) {
                const char* krow = (const char*)&sK[(b + i) * DP];
                u64 d0, d1;
                {
                    u64 a0, a1, a2, a3;
                    lds_v2u64(a0, a1, krow);
                    lds_v2u64(a2, a3, krow + 16);
                    d0 = fma2v(qv[0], a0, 0ull);
                    d1 = fma2v(qv[1], a1, 0ull);
                    d0 = fma2v(qv[2], a2, d0);
                    d1 = fma2v(qv[3], a3, d1);
                }
                {
                    u64 a0, a1, a2, a3;
                    lds_v2u64(a0, a1, krow + 32);
                    lds_v2u64(a2, a3, krow + 48);
                    d0 = fma2v(qv[4], a0, d0);
                    d1 = fma2v(qv[5], a1, d1);
                    d0 = fma2v(qv[6], a2, d0);
                    d1 = fma2v(qv[7], a3, d1);
                }
                {
                    u64 a0, a1, a2, a3;
                    lds_v2u64(a0, a1, krow + 64);
                    lds_v2u64(a2, a3, krow + 80);
                    d0 = fma2v(qv[8], a0, d0);
                    d1 = fma2v(qv[9], a1, d1);
                    d0 = fma2v(qv[10], a2, d0);
                    d1 = fma2v(qv[11], a3, d1);
                }
                {
                    u64 a0, a1;
                    lds_v2u64(a0, a1, krow + 96);
                    d0 = fma2v(qv[12], a0, d0);
                    d1 = fma2v(qv[13], a1, d1);
                }
                d0 = add2v(d0, d1);
                float lo, hi;
                unpack2(d0, lo, hi);
                float sc = fmaf(lo + hi, S2, -sY[b + i]);
                mask |= (sc > thr) ? (1u << i) : 0u;
            }
            // ---- one warp-wide union for the whole batch ----
            mask = __reduce_or_sync(0xffffffffu, mask);
            // ---- slow pass: only flagged keys ----
            while (mask) {
                int i = __ffs(mask) - 1;
                mask &= mask - 1;
                const char* krow = (const char*)&sK[(b + i) * DP];
                u64 kv[DP2];
#pragma unroll
                for (int p = 0; p < DP2 / 2; p++)
                    lds_v2u64(kv[2 * p], kv[2 * p + 1], krow + 16 * p);
                u64 d0 = fma2v(qv[0], kv[0], 0ull);
                u64 d1 = fma2v(qv[1], kv[1], 0ull);
#pragma unroll
                for (int j = 2; j < DP2; j += 2) {
                    d0 = fma2v(qv[j], kv[j], d0);
                    d1 = fma2v(qv[j + 1], kv[j + 1], d1);
                }
                d0 = add2v(d0, d1);
                float lo, hi;
                unpack2(d0, lo, hi);
                float sc = fmaf(lo + hi, S2, -sY[b + i]);

                if (sc > mmax) {            // rare rescale (peaked softmax)
                    float corr = ex2(mmax - sc);
                    u64 c2 = pack2(corr, corr);
#pragma unroll
                    for (int j = 0; j < DP2; j++) acc[j] = mul2v(acc[j], c2);
                    mmax = sc;
                }
                float p = ex2(sc - mmax);
                u64 p2 = pack2(p, p);
#pragma unroll
                for (int j = 0; j < DP2; j++)
                    acc[j] = fma2v(p2, kv[j], acc[j]);
            }
        }
        __syncthreads();
    }

    {
        int sidx = blockIdx.y * LQ + ql;
        g_pm[sidx] = mmax;
        ulonglong2* dst = (ulonglong2*)&g_pacc[(size_t)sidx * DP];
#pragma unroll
        for (int p = 0; p < DP2 / 2; p++) {
            ulonglong2 t;
            t.x = acc[2 * p]; t.y = acc[2 * p + 1];
            dst[p] = t;
        }
    }
}

// ---------------------------------------------------------------------------
// Kernel C: log-sum-exp merge of the SPLIT partials, normalize.
// o[27] = total softmax mass (from the K-pad trick)
// ---------------------------------------------------------------------------
__global__ void merge_kernel() {
    int q = blockIdx.x * blockDim.x + threadIdx.x;
    if (q >= LQ) return;
    float M = -CUDART_INF_F;
#pragma unroll
    for (int s = 0; s < SPLIT; s++) M = fmaxf(M, g_pm[s * LQ + q]);
    float o[DP];
#pragma unroll
    for (int j = 0; j < DP; j++) o[j] = 0.f;
#pragma unroll
    for (int s = 0; s < SPLIT; s++) {
        float w = ex2(g_pm[s * LQ + q] - M);
        const float4* src = (const float4*)&g_pacc[(size_t)(s * LQ + q) * DP];
#pragma unroll
        for (int p = 0; p < DP / 4; p++) {
            float4 t = src[p];
            o[4 * p]     = fmaf(t.x, w, o[4 * p]);
            o[4 * p + 1] = fmaf(t.y, w, o[4 * p + 1]);
            o[4 * p + 2] = fmaf(t.z, w, o[4 * p + 2]);
            o[4 * p + 3] = fmaf(t.w, w, o[4 * p + 3]);
        }
    }
    float inv = 1.0f / o[27];
#pragma unroll
    for (int p = 0; p < DP / 4; p++) {
        float4 t;
        t.x = o[4 * p] * inv; t.y = o[4 * p + 1] * inv;
        t.z = o[4 * p + 2] * inv; t.w = o[4 * p + 3] * inv;
        ((float4*)&g_outP[q * DP])[p] = t;
    }
}

// ---------------------------------------------------------------------------
// Kernel D: overlap-add fold with analytic contribution counts
// ---------------------------------------------------------------------------
__global__ void fold_kernel(float* __restrict__ out) {
    int idx = blockIdx.x * blockDim.x + threadIdx.x;
    if (idx >= 3 * 128 * 128) return;
    int c = idx / 16384;
    int h = (idx / 128) % 128;
    int w = idx % 128;
    int nh = min(h, 125) - max(0, h - 2) + 1;
    int nw = min(w, 125) - max(0, w - 2) + 1;
    float sum = 0.f;
#pragma unroll
    for (int ki = 0; ki < 3; ki++) {
        int ph = h - ki;
        if (ph < 0 || ph >= HO) continue;
#pragma unroll
        for (int kj = 0; kj < 3; kj++) {
            int pw = w - kj;
            if (pw < 0 || pw >= HO) continue;
            sum += g_outP[(ph * HO + pw) * DP + c * 9 + ki * 3 + kj];
        }
    }
    out[idx] = sum / (float)(nh * nw);
}

// ---------------------------------------------------------------------------
extern "C" void kernel_launch(void* const* d_in, const int* in_sizes, int n_in,
                              void* d_out, int out_size) {
    const float* x = (const float*)d_in[0];
    const float* y = (const float*)d_in[1];
    float* out = (float*)d_out;

    extract_kernel<<<(LQ + 255) / 256, 256>>>(x, y);
    dim3 grid(NQB, SPLIT);
    attn_kernel<<<grid, BQ>>>();
    merge_kernel<<<(LQ + 255) / 256, 256>>>();
    fold_kernel<<<(3 * 128 * 128 + 255) / 256, 256>>>(out);
}

// round 14
// speedup vs baseline: 1.1351x; 1.1351x over previous
#include <cuda_runtime.h>
#include <math_constants.h>

// Problem constants
#define LQ   15876          // L = 126*126 patches
#define HO   126
#define D    27
#define DP   28             // padded dim; K pad = 1.0 (ssum trick), Q pad = 0
#define SPLIT 9             // split-K over keys (15876 = 9 * 1764)
#define BQ   256            // threads per CTA (1 query per thread)
#define BK   252            // key tile in smem (1764 = 7 * 252, no tail)
#define BATCH 14            // keys per mask batch (252 = 18 * 14)
#define NQB  64             // 8x8 CTA tiles of 16x16 queries (covers 126x126)
#define CH   (LQ / SPLIT)   // 1764 keys per chunk
#define DP2  (DP / 2)       // 14 packed f32x2 values
#define SKIP_THR 18.0f      // log2 skip; measured dropped mass ~1e-9 at 22

typedef unsigned long long u64;

// Scratch (no allocations allowed -> device globals)
__device__ __align__(16) float g_K[LQ * DP];          // x patches (keys/vals)
__device__ __align__(16) float g_Q[LQ * DP];          // y patches (queries)
__device__ float g_yyc[LQ];                            // ||X_m||^2 * log2e/0.35
__device__ float g_pm[SPLIT * LQ];                     // partial max (log2 dom)
__device__ __align__(16) float g_pacc[SPLIT * LQ * DP]; // [..27] holds ssum
__device__ __align__(16) float g_outP[LQ * DP];        // attention out patches

__device__ __forceinline__ float ex2(float x) {
    float r;
    asm("ex2.approx.ftz.f32 %0, %1;" : "=f"(r) : "f"(x));
    return r;
}
__device__ __forceinline__ u64 pack2(float a, float b) {
    u64 r;
    asm("mov.b64 %0, {%1, %2};" : "=l"(r) : "f"(a), "f"(b));
    return r;
}
__device__ __forceinline__ void unpack2(u64 v, float& a, float& b) {
    asm("mov.b64 {%0, %1}, %2;" : "=f"(a), "=f"(b) : "l"(v));
}
// d = a*b + c  (packed 2x fp32)
__device__ __forceinline__ u64 fma2v(u64 a, u64 b, u64 c) {
    u64 d;
    asm("fma.rn.f32x2 %0, %1, %2, %3;" : "=l"(d) : "l"(a), "l"(b), "l"(c));
    return d;
}
__device__ __forceinline__ u64 add2v(u64 a, u64 b) {
    u64 d;
    asm("add.rn.f32x2 %0, %1, %2;" : "=l"(d) : "l"(a), "l"(b));
    return d;
}
__device__ __forceinline__ u64 mul2v(u64 a, u64 b) {
    u64 d;
    asm("mul.rn.f32x2 %0, %1, %2;" : "=l"(d) : "l"(a), "l"(b));
    return d;
}
// load two adjacent u64 (16B) from shared
__device__ __forceinline__ void lds_v2u64(u64& a, u64& b, const void* p) {
    asm("ld.shared.v2.b64 {%0, %1}, [%2];"
        : "=l"(a), "=l"(b) : "l"((size_t)__cvta_generic_to_shared(p)));
}

// ---------------------------------------------------------------------------
// Kernel A: patch extraction + key squared norms. K pad=1.0, Q pad=0.0
// ---------------------------------------------------------------------------
__global__ void extract_kernel(const float* __restrict__ x,
                               const float* __restrict__ y) {
    int m = blockIdx.x * blockDim.x + threadIdx.x;
    if (m >= LQ) return;
    int ph = m / HO, pw = m % HO;
    const float YSC = 1.4426950408889634f / 0.35f;   // log2e / (h^2 + 0.1)
    float yy = 0.f;
#pragma unroll
    for (int c = 0; c < 3; c++)
#pragma unroll
        for (int ki = 0; ki < 3; ki++)
#pragma unroll
            for (int kj = 0; kj < 3; kj++) {
                int j = c * 9 + ki * 3 + kj;
                float vx = x[c * 16384 + (ph + ki) * 128 + (pw + kj)];
                float vy = y[c * 16384 + (ph + ki) * 128 + (pw + kj)];
                g_K[m * DP + j] = vx;
                g_Q[m * DP + j] = vy;
                yy = fmaf(vx, vx, yy);
            }
    g_K[m * DP + 27] = 1.0f;     // ssum-in-accumulator trick
    g_Q[m * DP + 27] = 0.0f;     // keeps dot product exact
    g_yyc[m] = yy * YSC;
}

// ---------------------------------------------------------------------------
// Kernel B: flash attention, split-K, packed f32x2, BATCHED skip v2.
// Per 14-key batch:
//   fast pass:  14 independent dots -> sc[] kept in registers (no votes,
//               no branches, no fmax-vs-running-max per key)
//   threshold:  newmax = max(mmax, batch max); flag sc > newmax-THR
//               (tighter than the per-key running-max test)
//   one redux.sync.or -> warp-wide mask; one branch per batch
//   rescale:    once per batch, branch-free: acc *= ex2(mmax-newmax)
//   slow pass:  flagged keys only; reuse stored sc (no dot recompute),
//               reload kv (7 LDS) + 1 ex2 + 14 fma2
// acc[27] accumulates the softmax mass (K pad element = 1).
// ---------------------------------------------------------------------------
__global__ __launch_bounds__(BQ, 2) void attn_kernel() {
    __shared__ __align__(16) float sK[BK * DP];
    __shared__ float sY[BK];

    int tid = threadIdx.x;
    int w = tid >> 5;                       // warp 0..7
    int lane = tid & 31;
    // CTA tile: 16x16 queries at (bh*16, bw*16); warp subtile 4x8
    int bh = blockIdx.x >> 3, bw = blockIdx.x & 7;
    int qrow = min(bh * 16 + (w >> 1) * 4 + (lane >> 3), HO - 1);
    int qcol = min(bw * 16 + (w & 1) * 8 + (lane & 7), HO - 1);
    int ql = qrow * HO + qcol;

    int k0 = blockIdx.y * CH;

    const float S2 = 2.0f * 1.4426950408889634f / 0.35f;

    u64 qv[DP2];
#pragma unroll
    for (int p = 0; p < DP2 / 2; p++) {
        ulonglong2 t = ((const ulonglong2*)&g_Q[ql * DP])[p];
        qv[2 * p] = t.x; qv[2 * p + 1] = t.y;
    }
    u64 acc[DP2];
#pragma unroll
    for (int j = 0; j < DP2; j++) acc[j] = 0ull;
    float mmax = -CUDART_INF_F;

#pragma unroll 1
    for (int tile = 0; tile < CH / BK; tile++) {
        int kt = k0 + tile * BK;
        for (int t = tid; t < BK * (DP / 4); t += BQ) {
            ((float4*)sK)[t] = ((const float4*)g_K)[kt * (DP / 4) + t];
        }
        for (int t = tid; t < BK; t += BQ) sY[t] = g_yyc[kt + t];
        __syncthreads();

#pragma unroll 1
        for (int b = 0; b < BK; b += BATCH) {
            float sc[BATCH];
            // ---- fast pass: 14 independent dots ----
#pragma unroll
            for (int i = 0; i < BATCH; i++) {
                const char* krow = (const char*)&sK[(b + i) * DP];
                u64 kv[DP2];
#pragma unroll
                for (int p = 0; p < DP2 / 2; p++)
                    lds_v2u64(kv[2 * p], kv[2 * p + 1], krow + 16 * p);
                u64 d0 = fma2v(qv[0], kv[0], 0ull);
                u64 d1 = fma2v(qv[1], kv[1], 0ull);
#pragma unroll
                for (int j = 2; j < DP2; j += 2) {
                    d0 = fma2v(qv[j], kv[j], d0);
                    d1 = fma2v(qv[j + 1], kv[j + 1], d1);
                }
                d0 = add2v(d0, d1);
                float lo, hi;
                unpack2(d0, lo, hi);
                sc[i] = fmaf(lo + hi, S2, -sY[b + i]);
            }
            // ---- batch max, final threshold, mask ----
            float bmax = sc[0];
#pragma unroll
            for (int i = 1; i < BATCH; i++) bmax = fmaxf(bmax, sc[i]);
            float newmax = fmaxf(mmax, bmax);
            float thr = newmax - SKIP_THR;
            unsigned mask = 0u;
#pragma unroll
            for (int i = 0; i < BATCH; i++)
                mask |= (sc[i] > thr) ? (1u << i) : 0u;
            mask = __reduce_or_sync(0xffffffffu, mask);

            if (mask) {
                // branch-free rescale, once per batch (corr<=1; corr=0
                // when mmax=-inf which matches acc==0)
                float corr = ex2(mmax - newmax);
                u64 c2 = pack2(corr, corr);
#pragma unroll
                for (int j = 0; j < DP2; j++) acc[j] = mul2v(acc[j], c2);
                mmax = newmax;
                // ---- slow pass: flagged keys, reuse stored scores ----
                while (mask) {
                    int i = __ffs(mask) - 1;
                    mask &= mask - 1;
                    const char* krow = (const char*)&sK[(b + i) * DP];
                    float p = ex2(sc[i] - mmax);
                    u64 p2 = pack2(p, p);
#pragma unroll
                    for (int jj = 0; jj < DP2; jj += 2) {
                        u64 a, bb;
                        lds_v2u64(a, bb, krow + 16 * (jj / 2));
                        acc[jj]     = fma2v(p2, a, acc[jj]);
                        acc[jj + 1] = fma2v(p2, bb, acc[jj + 1]);
                    }
                }
            }
        }
        __syncthreads();
    }

    {
        int sidx = blockIdx.y * LQ + ql;
        g_pm[sidx] = mmax;
        ulonglong2* dst = (ulonglong2*)&g_pacc[(size_t)sidx * DP];
#pragma unroll
        for (int p = 0; p < DP2 / 2; p++) {
            ulonglong2 t;
            t.x = acc[2 * p]; t.y = acc[2 * p + 1];
            dst[p] = t;
        }
    }
}

// ---------------------------------------------------------------------------
// Kernel C: log-sum-exp merge of the SPLIT partials, normalize.
// o[27] = total softmax mass (from the K-pad trick)
// ---------------------------------------------------------------------------
__global__ void merge_kernel() {
    int q = blockIdx.x * blockDim.x + threadIdx.x;
    if (q >= LQ) return;
    float M = -CUDART_INF_F;
#pragma unroll
    for (int s = 0; s < SPLIT; s++) M = fmaxf(M, g_pm[s * LQ + q]);
    float o[DP];
#pragma unroll
    for (int j = 0; j < DP; j++) o[j] = 0.f;
#pragma unroll
    for (int s = 0; s < SPLIT; s++) {
        float w = ex2(g_pm[s * LQ + q] - M);
        const float4* src = (const float4*)&g_pacc[(size_t)(s * LQ + q) * DP];
#pragma unroll
        for (int p = 0; p < DP / 4; p++) {
            float4 t = src[p];
            o[4 * p]     = fmaf(t.x, w, o[4 * p]);
            o[4 * p + 1] = fmaf(t.y, w, o[4 * p + 1]);
            o[4 * p + 2] = fmaf(t.z, w, o[4 * p + 2]);
            o[4 * p + 3] = fmaf(t.w, w, o[4 * p + 3]);
        }
    }
    float inv = 1.0f / o[27];
#pragma unroll
    for (int p = 0; p < DP / 4; p++) {
        float4 t;
        t.x = o[4 * p] * inv; t.y = o[4 * p + 1] * inv;
        t.z = o[4 * p + 2] * inv; t.w = o[4 * p + 3] * inv;
        ((float4*)&g_outP[q * DP])[p] = t;
    }
}

// ---------------------------------------------------------------------------
// Kernel D: overlap-add fold with analytic contribution counts
// ---------------------------------------------------------------------------
__global__ void fold_kernel(float* __restrict__ out) {
    int idx = blockIdx.x * blockDim.x + threadIdx.x;
    if (idx >= 3 * 128 * 128) return;
    int c = idx / 16384;
    int h = (idx / 128) % 128;
    int w = idx % 128;
    int nh = min(h, 125) - max(0, h - 2) + 1;
    int nw = min(w, 125) - max(0, w - 2) + 1;
    float sum = 0.f;
#pragma unroll
    for (int ki = 0; ki < 3; ki++) {
        int ph = h - ki;
        if (ph < 0 || ph >= HO) continue;
#pragma unroll
        for (int kj = 0; kj < 3; kj++) {
            int pw = w - kj;
            if (pw < 0 || pw >= HO) continue;
            sum += g_outP[(ph * HO + pw) * DP + c * 9 + ki * 3 + kj];
        }
    }
    out[idx] = sum / (float)(nh * nw);
}

// ---------------------------------------------------------------------------
extern "C" void kernel_launch(void* const* d_in, const int* in_sizes, int n_in,
                              void* d_out, int out_size) {
    const float* x = (const float*)d_in[0];
    const float* y = (const float*)d_in[1];
    float* out = (float*)d_out;

    extract_kernel<<<(LQ + 255) / 256, 256>>>(x, y);
    dim3 grid(NQB, SPLIT);
    attn_kernel<<<grid, BQ>>>();
    merge_kernel<<<(LQ + 255) / 256, 256>>>();
    fold_kernel<<<(3 * 128 * 128 + 255) / 256, 256>>>(out);
}